// round 4
// baseline (speedup 1.0000x reference)
#include <cuda_runtime.h>
#include <math.h>

#define E_N 500000
#define G_N 256
#define H_N 256
#define H2_N 512
#define EPS_F 1.1920929e-07f
#define LOG_EPS -15.942385f

// ---------------- scratch (device globals; no allocation allowed) ------------
__device__ float d_v_edge[H_N];        // att_vec @ W_edge
__device__ float d_v_query[H_N];       // att_vec @ W_query
__device__ float d_q_att[G_N];         // question · v_query  per graph
__device__ float d_att_raw[E_N];       // post-leaky/bonus attention logits
__device__ float d_sum_tok[G_N * H_N]; // segment sums of raw edge tokens
__device__ float d_maxg[G_N];
__device__ float d_logsum[G_N];
__device__ float d_invden[G_N];
__device__ float d_xn[G_N * H2_N];     // LayerNorm output
__device__ float d_h1[G_N * H_N];      // GELU(MLP hidden)

// ---------------- K0: zero segment-sum buffer --------------------------------
__global__ void k0_zero() {
    int i = blockIdx.x * blockDim.x + threadIdx.x;
    if (i < G_N * H_N) d_sum_tok[i] = 0.0f;
}

// ---------------- K1: v_edge / v_query (att_vec @ W) -------------------------
__global__ void k1_vvec(const float* __restrict__ W_edge,
                        const float* __restrict__ W_query,
                        const float* __restrict__ att_vec) {
    __shared__ float a[H_N];
    int t = threadIdx.x;
    a[t] = att_vec[t];
    __syncthreads();
    float ve = 0.f, vq = 0.f;
    #pragma unroll 8
    for (int j = 0; j < H_N; ++j) {
        float aj = a[j];
        ve = fmaf(aj, W_edge[j * H_N + t], ve);
        vq = fmaf(aj, W_query[j * H_N + t], vq);
    }
    d_v_edge[t] = ve;
    d_v_query[t] = vq;
}

// ---------------- K2: q_att[g] = question[g] · v_query  (warp per graph) -----
__global__ void k2_qatt(const float* __restrict__ q) {
    int w = (blockIdx.x * blockDim.x + threadIdx.x) >> 5;
    int lane = threadIdx.x & 31;
    if (w >= G_N) return;
    const float4* q4 = (const float4*)(q + (size_t)w * H_N);
    const float4* v4 = (const float4*)d_v_query;
    float s = 0.f;
    #pragma unroll
    for (int k = 0; k < 2; ++k) {
        float4 t = q4[lane + 32 * k];
        float4 v = v4[lane + 32 * k];
        s += t.x * v.x + t.y * v.y + t.z * v.z + t.w * v.w;
    }
    #pragma unroll
    for (int o = 16; o; o >>= 1) s += __shfl_xor_sync(0xffffffffu, s, o);
    if (lane == 0) d_q_att[w] = s;
}

// ---------------- K3: dominant streaming pass over edge_tokens ---------------
#define K3_BLOCK 256
#define K3_GRID  512
#define K3_WARPS (K3_GRID * (K3_BLOCK / 32))

__global__ __launch_bounds__(K3_BLOCK) void k3_edges(
        const float* __restrict__ tok,
        const int* __restrict__ batch,
        const int* __restrict__ sel) {
    int warp = (blockIdx.x * blockDim.x + threadIdx.x) >> 5;
    int lane = threadIdx.x & 31;
    const int chunk = (E_N + K3_WARPS - 1) / K3_WARPS;
    int e0 = warp * chunk;
    int e1 = min(e0 + chunk, E_N);
    if (e0 >= e1) return;

    // this lane's slice of v_edge: cols [4*lane..4*lane+3] and [128+4*lane..]
    float4 v0 = ((const float4*)d_v_edge)[lane];
    float4 v1 = ((const float4*)d_v_edge)[lane + 32];

    float4 a0 = make_float4(0.f, 0.f, 0.f, 0.f);
    float4 a1 = make_float4(0.f, 0.f, 0.f, 0.f);

    const float4* base = (const float4*)tok;
    float4 t0 = __ldcs(base + (size_t)e0 * 64 + lane);
    float4 t1 = __ldcs(base + (size_t)e0 * 64 + 32 + lane);
    int g  = batch[e0];
    int cg = g;

    for (int e = e0; e < e1; ++e) {
        // prefetch next edge (MLP ~2 per warp)
        float4 n0, n1; int ng = cg;
        if (e + 1 < e1) {
            n0 = __ldcs(base + (size_t)(e + 1) * 64 + lane);
            n1 = __ldcs(base + (size_t)(e + 1) * 64 + 32 + lane);
            ng = batch[e + 1];
        }
        if (g != cg) {  // segment boundary: flush partial sums
            float* dst = d_sum_tok + (size_t)cg * H_N;
            atomicAdd(&dst[4 * lane + 0], a0.x);
            atomicAdd(&dst[4 * lane + 1], a0.y);
            atomicAdd(&dst[4 * lane + 2], a0.z);
            atomicAdd(&dst[4 * lane + 3], a0.w);
            atomicAdd(&dst[128 + 4 * lane + 0], a1.x);
            atomicAdd(&dst[128 + 4 * lane + 1], a1.y);
            atomicAdd(&dst[128 + 4 * lane + 2], a1.z);
            atomicAdd(&dst[128 + 4 * lane + 3], a1.w);
            a0 = make_float4(0.f, 0.f, 0.f, 0.f);
            a1 = make_float4(0.f, 0.f, 0.f, 0.f);
            cg = g;
        }
        a0.x += t0.x; a0.y += t0.y; a0.z += t0.z; a0.w += t0.w;
        a1.x += t1.x; a1.y += t1.y; a1.z += t1.z; a1.w += t1.w;

        float d = t0.x * v0.x;
        d = fmaf(t0.y, v0.y, d); d = fmaf(t0.z, v0.z, d); d = fmaf(t0.w, v0.w, d);
        d = fmaf(t1.x, v1.x, d); d = fmaf(t1.y, v1.y, d);
        d = fmaf(t1.z, v1.z, d); d = fmaf(t1.w, v1.w, d);
        #pragma unroll
        for (int o = 16; o; o >>= 1) d += __shfl_xor_sync(0xffffffffu, d, o);

        if (lane == 0) {
            float att = d + d_q_att[g];
            att = att > 0.f ? att : 0.2f * att;         // LeakyReLU(0.2)
            if (sel[e] == 0) att += 0.5f;               // frontier bonus (candidate)
            d_att_raw[e] = att;
        }
        t0 = n0; t1 = n1; g = ng;
    }
    // final flush
    float* dst = d_sum_tok + (size_t)cg * H_N;
    atomicAdd(&dst[4 * lane + 0], a0.x);
    atomicAdd(&dst[4 * lane + 1], a0.y);
    atomicAdd(&dst[4 * lane + 2], a0.z);
    atomicAdd(&dst[4 * lane + 3], a0.w);
    atomicAdd(&dst[128 + 4 * lane + 0], a1.x);
    atomicAdd(&dst[128 + 4 * lane + 1], a1.y);
    atomicAdd(&dst[128 + 4 * lane + 2], a1.z);
    atomicAdd(&dst[128 + 4 * lane + 3], a1.w);
}

// ---------------- K4: per-graph max + masked exp-sum (block per graph) -------
__global__ void k4_softmax(const int* __restrict__ batch,
                           const int* __restrict__ sel) {
    int gidx = blockIdx.x;
    int t = threadIdx.x;
    // binary search the sorted edge_batch for [start, end)
    int lo = 0, hi = E_N;
    while (lo < hi) { int m = (lo + hi) >> 1; if (batch[m] < gidx) lo = m + 1; else hi = m; }
    int start = lo;
    lo = start; hi = E_N;
    while (lo < hi) { int m = (lo + hi) >> 1; if (batch[m] < gidx + 1) lo = m + 1; else hi = m; }
    int end = lo;

    __shared__ float red[256];
    float mx = -INFINITY;
    for (int e = start + t; e < end; e += 256) mx = fmaxf(mx, d_att_raw[e]);
    red[t] = mx; __syncthreads();
    for (int s = 128; s; s >>= 1) { if (t < s) red[t] = fmaxf(red[t], red[t + s]); __syncthreads(); }
    mx = red[0];
    __syncthreads();

    float sm = 0.f;
    for (int e = start + t; e < end; e += 256)
        if (sel[e] == 0) sm += expf(d_att_raw[e] - mx);
    red[t] = sm; __syncthreads();
    for (int s = 128; s; s >>= 1) { if (t < s) red[t] += red[t + s]; __syncthreads(); }

    if (t == 0) {
        int cnt = end - start;
        d_maxg[gidx]   = (cnt > 0) ? mx : 0.f;
        d_logsum[gidx] = logf(fmaxf(red[0], EPS_F));
        d_invden[gidx] = 1.0f / (float)max(cnt, 1);
    }
}

// ---------------- K5: pooled = (sum_tok @ W_edge^T) * invden  (tiled GEMM) ---
__global__ void k5_pool(const float* __restrict__ W_edge,
                        float* __restrict__ out_pool) {
    __shared__ float As[32][33], Ws[32][33];
    int tx = threadIdx.x, ty = threadIdx.y;
    float acc = 0.f;
    for (int kt = 0; kt < H_N; kt += 32) {
        As[ty][tx] = d_sum_tok[(blockIdx.y * 32 + ty) * H_N + kt + tx];
        Ws[ty][tx] = W_edge[(blockIdx.x * 32 + ty) * H_N + kt + tx];
        __syncthreads();
        #pragma unroll
        for (int kk = 0; kk < 32; ++kk) acc = fmaf(As[ty][kk], Ws[tx][kk], acc);
        __syncthreads();
    }
    int g = blockIdx.y * 32 + ty, j = blockIdx.x * 32 + tx;
    out_pool[g * H_N + j] = acc * d_invden[g];
}

// ---------------- K6a: LayerNorm over concat(pooled, question) ---------------
__global__ void k6a_ln(const float* __restrict__ pooled,
                       const float* __restrict__ q,
                       const float* __restrict__ ln_g,
                       const float* __restrict__ ln_b) {
    int g = blockIdx.x, t = threadIdx.x;
    float x0 = pooled[g * H_N + t];
    float x1 = q[g * H_N + t];
    __shared__ float rs[256], rss[256];
    rs[t]  = x0 + x1;
    rss[t] = x0 * x0 + x1 * x1;
    __syncthreads();
    for (int s = 128; s; s >>= 1) {
        if (t < s) { rs[t] += rs[t + s]; rss[t] += rss[t + s]; }
        __syncthreads();
    }
    float mu  = rs[0] * (1.0f / 512.0f);
    float var = rss[0] * (1.0f / 512.0f) - mu * mu;
    float inv = rsqrtf(var + 1e-5f);
    d_xn[g * H2_N + t]        = (x0 - mu) * inv * ln_g[t]        + ln_b[t];
    d_xn[g * H2_N + 256 + t]  = (x1 - mu) * inv * ln_g[256 + t]  + ln_b[256 + t];
}

// ---------------- K6b: h1 = GELU(xn @ W1^T + b1)  (tiled GEMM, K=512) --------
__global__ void k6b_mlp(const float* __restrict__ W1,
                        const float* __restrict__ b1) {
    __shared__ float As[32][33], Ws[32][33];
    int tx = threadIdx.x, ty = threadIdx.y;
    float acc = 0.f;
    for (int kt = 0; kt < H2_N; kt += 32) {
        As[ty][tx] = d_xn[(blockIdx.y * 32 + ty) * H2_N + kt + tx];
        Ws[ty][tx] = W1[(blockIdx.x * 32 + ty) * H2_N + kt + tx];
        __syncthreads();
        #pragma unroll
        for (int kk = 0; kk < 32; ++kk) acc = fmaf(As[ty][kk], Ws[tx][kk], acc);
        __syncthreads();
    }
    int g = blockIdx.y * 32 + ty, j = blockIdx.x * 32 + tx;
    float x = acc + b1[j];
    float gl = 0.5f * x * (1.0f + erff(x * 0.70710678118654752f)); // exact GELU
    d_h1[g * H_N + j] = gl;
}

// ---------------- K6c: stop_logits = h1 · W2 + b2  (warp per graph) ----------
__global__ void k6c_stop(const float* __restrict__ W2,
                         const float* __restrict__ b2,
                         float* __restrict__ out_stop) {
    int w = (blockIdx.x * blockDim.x + threadIdx.x) >> 5;
    int lane = threadIdx.x & 31;
    if (w >= G_N) return;
    const float4* h4 = (const float4*)(d_h1 + (size_t)w * H_N);
    const float4* w4 = (const float4*)W2;
    float s = 0.f;
    #pragma unroll
    for (int k = 0; k < 2; ++k) {
        float4 a = h4[lane + 32 * k];
        float4 b = w4[lane + 32 * k];
        s += a.x * b.x + a.y * b.y + a.z * b.z + a.w * b.w;
    }
    #pragma unroll
    for (int o = 16; o; o >>= 1) s += __shfl_xor_sync(0xffffffffu, s, o);
    if (lane == 0) out_stop[w] = s + b2[0];
}

// ---------------- K7: final edge logits in log-space -------------------------
__global__ void k7_logits(const int* __restrict__ batch,
                          const int* __restrict__ sel,
                          float* __restrict__ out) {
    int i = blockIdx.x * blockDim.x + threadIdx.x;
    int stride = gridDim.x * blockDim.x;
    for (int e = i; e < E_N; e += stride) {
        int g = batch[e];
        float v = LOG_EPS;
        if (sel[e] == 0)
            v = fmaxf(d_att_raw[e] - d_maxg[g] - d_logsum[g], LOG_EPS);
        out[e] = v;
    }
}

// ---------------- launch -----------------------------------------------------
extern "C" void kernel_launch(void* const* d_in, const int* in_sizes, int n_in,
                              void* d_out, int out_size) {
    const float* edge_tokens     = (const float*)d_in[0];
    const float* question_tokens = (const float*)d_in[1];
    const int*   edge_batch      = (const int*)d_in[2];
    const int*   selected_mask   = (const int*)d_in[3];   // bool promoted to int32
    const float* W_edge          = (const float*)d_in[4];
    const float* W_query         = (const float*)d_in[5];
    const float* att_vec         = (const float*)d_in[6];
    const float* ln_g            = (const float*)d_in[7];
    const float* ln_b            = (const float*)d_in[8];
    const float* W1              = (const float*)d_in[9];
    const float* b1              = (const float*)d_in[10];
    const float* W2              = (const float*)d_in[11];
    const float* b2              = (const float*)d_in[12];

    float* out         = (float*)d_out;
    float* out_edge    = out;                 // [E]
    float* out_stop    = out + E_N;           // [G]
    float* out_pooled  = out + E_N + G_N;     // [G, H]

    k0_zero<<<(G_N * H_N + 255) / 256, 256>>>();
    k1_vvec<<<1, H_N>>>(W_edge, W_query, att_vec);
    k2_qatt<<<(G_N * 32 + 255) / 256, 256>>>(question_tokens);
    k3_edges<<<K3_GRID, K3_BLOCK>>>(edge_tokens, edge_batch, selected_mask);
    k4_softmax<<<G_N, 256>>>(edge_batch, selected_mask);
    k5_pool<<<dim3(8, 8), dim3(32, 32)>>>(W_edge, out_pooled);
    k6a_ln<<<G_N, 256>>>(out_pooled, question_tokens, ln_g, ln_b);
    k6b_mlp<<<dim3(8, 8), dim3(32, 32)>>>(W1, b1);
    k6c_stop<<<(G_N * 32 + 255) / 256, 256>>>(W2, b2, out_stop);
    k7_logits<<<512, 256>>>(edge_batch, selected_mask, out_edge);
}

// round 5
// speedup vs baseline: 1.1500x; 1.1500x over previous
#include <cuda_runtime.h>
#include <math.h>

#define E_N 500000
#define G_N 256
#define H_N 256
#define H2_N 512
#define EPS_F 1.1920929e-07f
#define LOG_EPS -15.942385f

// ---------------- scratch (device globals; no allocation allowed) ------------
__device__ float d_v_edge[H_N];        // att_vec @ W_edge
__device__ float d_v_query[H_N];       // att_vec @ W_query
__device__ float d_q_att[G_N];         // question · v_query  per graph
__device__ float d_att_raw[E_N];       // post-leaky/bonus attention logits
__device__ float d_sum_tok[G_N * H_N]; // segment sums of raw edge tokens
__device__ int   d_seg[G_N + 1];       // segment bounds (sorted edge_batch)
__device__ float d_invden[G_N];
__device__ float d_xn[G_N * H2_N];     // LayerNorm output
__device__ float d_h1[G_N * H_N];      // GELU(MLP hidden)

// ---------------- kA: v_edge / v_query (parallel, j-split) + zero sum_tok ----
// grid (8,4), block 256.
//   y==0: v_edge cols [bx*32, +32)   y==1: v_query cols
//   y==2,3: zero d_sum_tok (16 blocks grid-stride)
__global__ void kA_prep(const float* __restrict__ W_edge,
                        const float* __restrict__ W_query,
                        const float* __restrict__ att_vec) {
    int y = blockIdx.y;
    int tid = threadIdx.x;
    if (y >= 2) {
        int idx = (((y - 2) * 8) + blockIdx.x) * 256 + tid;
        for (int i = idx; i < G_N * H_N; i += 16 * 256) d_sum_tok[i] = 0.0f;
        return;
    }
    const float* W = (y == 0) ? W_edge : W_query;
    float* v       = (y == 0) ? d_v_edge : d_v_query;
    __shared__ float a[H_N];
    __shared__ float part[8][32];
    a[tid] = att_vec[tid];
    __syncthreads();
    int tt = tid & 31, jg = tid >> 5;
    int t0 = blockIdx.x * 32 + tt;
    float s = 0.f;
    #pragma unroll 8
    for (int j = jg * 32; j < jg * 32 + 32; ++j)
        s = fmaf(a[j], W[j * H_N + t0], s);
    part[jg][tt] = s;
    __syncthreads();
    if (jg == 0) {
        float r = part[0][tt] + part[1][tt] + part[2][tt] + part[3][tt]
                + part[4][tt] + part[5][tt] + part[6][tt] + part[7][tt];
        v[t0] = r;
    }
}

// ---------------- kB: q_att (blocks 0..31) + segment bounds (blocks 32..255) -
__global__ void kB_qatt_seg(const float* __restrict__ q,
                            const int* __restrict__ batch) {
    int b = blockIdx.x;
    if (b < 32) {
        int w = b * 8 + (threadIdx.x >> 5);  // graph index
        int lane = threadIdx.x & 31;
        const float4* q4 = (const float4*)(q + (size_t)w * H_N);
        const float4* v4 = (const float4*)d_v_query;
        float s = 0.f;
        #pragma unroll
        for (int k = 0; k < 2; ++k) {
            float4 t = q4[lane + 32 * k];
            float4 v = v4[lane + 32 * k];
            s += t.x * v.x + t.y * v.y + t.z * v.z + t.w * v.w;
        }
        #pragma unroll
        for (int o = 16; o; o >>= 1) s += __shfl_xor_sync(0xffffffffu, s, o);
        if (lane == 0) d_q_att[w] = s;
    } else {
        int idx = (b - 32) * 256 + threadIdx.x;
        int stride = (gridDim.x - 32) * 256;
        for (int e = idx; e < E_N; e += stride) {
            int bc = batch[e];
            int bp = (e == 0) ? -1 : batch[e - 1];
            for (int g = bp + 1; g <= bc; ++g) d_seg[g] = e;
            if (e == E_N - 1)
                for (int g = bc + 1; g <= G_N; ++g) d_seg[g] = E_N;
        }
    }
}

// ---------------- K3: dominant streaming pass over edge_tokens ---------------
#define K3_BLOCK 256
#define K3_GRID  592                    // 4 blocks/SM x 148 SMs (reg-limit ceiling)
#define K3_WARPS (K3_GRID * (K3_BLOCK / 32))

__global__ __launch_bounds__(K3_BLOCK) void k3_edges(
        const float* __restrict__ tok,
        const int* __restrict__ batch,
        const int* __restrict__ sel) {
    int warp = (blockIdx.x * blockDim.x + threadIdx.x) >> 5;
    int lane = threadIdx.x & 31;
    const int chunk = (E_N + K3_WARPS - 1) / K3_WARPS;
    int e0 = warp * chunk;
    int e1 = min(e0 + chunk, E_N);
    if (e0 >= e1) return;

    float4 v0 = ((const float4*)d_v_edge)[lane];
    float4 v1 = ((const float4*)d_v_edge)[lane + 32];

    float4 a0 = make_float4(0.f, 0.f, 0.f, 0.f);
    float4 a1 = make_float4(0.f, 0.f, 0.f, 0.f);

    const float4* base = (const float4*)tok;
    float4 t0 = __ldcs(base + (size_t)e0 * 64 + lane);
    float4 t1 = __ldcs(base + (size_t)e0 * 64 + 32 + lane);
    int g  = batch[e0];
    int cg = g;

    for (int e = e0; e < e1; ++e) {
        float4 n0, n1; int ng = cg;
        if (e + 1 < e1) {
            n0 = __ldcs(base + (size_t)(e + 1) * 64 + lane);
            n1 = __ldcs(base + (size_t)(e + 1) * 64 + 32 + lane);
            ng = batch[e + 1];
        }
        if (g != cg) {  // segment boundary: flush partial sums
            float* dst = d_sum_tok + (size_t)cg * H_N;
            atomicAdd(&dst[4 * lane + 0], a0.x);
            atomicAdd(&dst[4 * lane + 1], a0.y);
            atomicAdd(&dst[4 * lane + 2], a0.z);
            atomicAdd(&dst[4 * lane + 3], a0.w);
            atomicAdd(&dst[128 + 4 * lane + 0], a1.x);
            atomicAdd(&dst[128 + 4 * lane + 1], a1.y);
            atomicAdd(&dst[128 + 4 * lane + 2], a1.z);
            atomicAdd(&dst[128 + 4 * lane + 3], a1.w);
            a0 = make_float4(0.f, 0.f, 0.f, 0.f);
            a1 = make_float4(0.f, 0.f, 0.f, 0.f);
            cg = g;
        }
        a0.x += t0.x; a0.y += t0.y; a0.z += t0.z; a0.w += t0.w;
        a1.x += t1.x; a1.y += t1.y; a1.z += t1.z; a1.w += t1.w;

        float d = t0.x * v0.x;
        d = fmaf(t0.y, v0.y, d); d = fmaf(t0.z, v0.z, d); d = fmaf(t0.w, v0.w, d);
        d = fmaf(t1.x, v1.x, d); d = fmaf(t1.y, v1.y, d);
        d = fmaf(t1.z, v1.z, d); d = fmaf(t1.w, v1.w, d);
        #pragma unroll
        for (int o = 16; o; o >>= 1) d += __shfl_xor_sync(0xffffffffu, d, o);

        if (lane == 0) {
            float att = d + d_q_att[g];
            att = att > 0.f ? att : 0.2f * att;         // LeakyReLU(0.2)
            if (sel[e] == 0) att += 0.5f;               // frontier bonus
            d_att_raw[e] = att;
        }
        t0 = n0; t1 = n1; g = ng;
    }
    float* dst = d_sum_tok + (size_t)cg * H_N;
    atomicAdd(&dst[4 * lane + 0], a0.x);
    atomicAdd(&dst[4 * lane + 1], a0.y);
    atomicAdd(&dst[4 * lane + 2], a0.z);
    atomicAdd(&dst[4 * lane + 3], a0.w);
    atomicAdd(&dst[128 + 4 * lane + 0], a1.x);
    atomicAdd(&dst[128 + 4 * lane + 1], a1.y);
    atomicAdd(&dst[128 + 4 * lane + 2], a1.z);
    atomicAdd(&dst[128 + 4 * lane + 3], a1.w);
}

// ---------------- K4: softmax stats + edge logits, fused (block per graph) ---
__global__ void k4_fused(const int* __restrict__ sel,
                         float* __restrict__ out_edge) {
    int gi = blockIdx.x, t = threadIdx.x;
    int start = d_seg[gi], end = d_seg[gi + 1];

    __shared__ float red[256];
    float mx = -INFINITY;
    for (int e = start + t; e < end; e += 256) mx = fmaxf(mx, d_att_raw[e]);
    red[t] = mx; __syncthreads();
    for (int s = 128; s; s >>= 1) { if (t < s) red[t] = fmaxf(red[t], red[t + s]); __syncthreads(); }
    mx = red[0];
    __syncthreads();

    float sm = 0.f;
    for (int e = start + t; e < end; e += 256)
        if (sel[e] == 0) sm += expf(d_att_raw[e] - mx);
    red[t] = sm; __syncthreads();
    for (int s = 128; s; s >>= 1) { if (t < s) red[t] += red[t + s]; __syncthreads(); }
    float sub = mx + logf(fmaxf(red[0], EPS_F));

    if (t == 0) d_invden[gi] = 1.0f / (float)max(end - start, 1);

    for (int e = start + t; e < end; e += 256) {
        float v = LOG_EPS;
        if (sel[e] == 0)
            v = fmaxf(d_att_raw[e] - sub, LOG_EPS);
        out_edge[e] = v;
    }
}

// ---------------- K5: pooled = (sum_tok @ W_edge^T) * invden  (tiled GEMM) ---
__global__ void k5_pool(const float* __restrict__ W_edge,
                        float* __restrict__ out_pool) {
    __shared__ float As[32][33], Ws[32][33];
    int tx = threadIdx.x, ty = threadIdx.y;
    float acc = 0.f;
    for (int kt = 0; kt < H_N; kt += 32) {
        As[ty][tx] = d_sum_tok[(blockIdx.y * 32 + ty) * H_N + kt + tx];
        Ws[ty][tx] = W_edge[(blockIdx.x * 32 + ty) * H_N + kt + tx];
        __syncthreads();
        #pragma unroll
        for (int kk = 0; kk < 32; ++kk) acc = fmaf(As[ty][kk], Ws[tx][kk], acc);
        __syncthreads();
    }
    int g = blockIdx.y * 32 + ty, j = blockIdx.x * 32 + tx;
    out_pool[g * H_N + j] = acc * d_invden[g];
}

// ---------------- K6a: LayerNorm over concat(pooled, question) ---------------
__global__ void k6a_ln(const float* __restrict__ pooled,
                       const float* __restrict__ q,
                       const float* __restrict__ ln_g,
                       const float* __restrict__ ln_b) {
    int g = blockIdx.x, t = threadIdx.x;
    float x0 = pooled[g * H_N + t];
    float x1 = q[g * H_N + t];
    __shared__ float rs[256], rss[256];
    rs[t]  = x0 + x1;
    rss[t] = x0 * x0 + x1 * x1;
    __syncthreads();
    for (int s = 128; s; s >>= 1) {
        if (t < s) { rs[t] += rs[t + s]; rss[t] += rss[t + s]; }
        __syncthreads();
    }
    float mu  = rs[0] * (1.0f / 512.0f);
    float var = rss[0] * (1.0f / 512.0f) - mu * mu;
    float inv = rsqrtf(var + 1e-5f);
    d_xn[g * H2_N + t]        = (x0 - mu) * inv * ln_g[t]        + ln_b[t];
    d_xn[g * H2_N + 256 + t]  = (x1 - mu) * inv * ln_g[256 + t]  + ln_b[256 + t];
}

// ---------------- K6b: h1 = GELU(xn @ W1^T + b1)  (tiled GEMM, K=512) --------
__global__ void k6b_mlp(const float* __restrict__ W1,
                        const float* __restrict__ b1) {
    __shared__ float As[32][33], Ws[32][33];
    int tx = threadIdx.x, ty = threadIdx.y;
    float acc = 0.f;
    for (int kt = 0; kt < H2_N; kt += 32) {
        As[ty][tx] = d_xn[(blockIdx.y * 32 + ty) * H2_N + kt + tx];
        Ws[ty][tx] = W1[(blockIdx.x * 32 + ty) * H2_N + kt + tx];
        __syncthreads();
        #pragma unroll
        for (int kk = 0; kk < 32; ++kk) acc = fmaf(As[ty][kk], Ws[tx][kk], acc);
        __syncthreads();
    }
    int g = blockIdx.y * 32 + ty, j = blockIdx.x * 32 + tx;
    float x = acc + b1[j];
    float gl = 0.5f * x * (1.0f + erff(x * 0.70710678118654752f)); // exact GELU
    d_h1[g * H_N + j] = gl;
}

// ---------------- K6c: stop_logits = h1 · W2 + b2  (warp per graph) ----------
__global__ void k6c_stop(const float* __restrict__ W2,
                         const float* __restrict__ b2,
                         float* __restrict__ out_stop) {
    int w = (blockIdx.x * blockDim.x + threadIdx.x) >> 5;
    int lane = threadIdx.x & 31;
    if (w >= G_N) return;
    const float4* h4 = (const float4*)(d_h1 + (size_t)w * H_N);
    const float4* w4 = (const float4*)W2;
    float s = 0.f;
    #pragma unroll
    for (int k = 0; k < 2; ++k) {
        float4 a = h4[lane + 32 * k];
        float4 b = w4[lane + 32 * k];
        s += a.x * b.x + a.y * b.y + a.z * b.z + a.w * b.w;
    }
    #pragma unroll
    for (int o = 16; o; o >>= 1) s += __shfl_xor_sync(0xffffffffu, s, o);
    if (lane == 0) out_stop[w] = s + b2[0];
}

// ---------------- launch -----------------------------------------------------
extern "C" void kernel_launch(void* const* d_in, const int* in_sizes, int n_in,
                              void* d_out, int out_size) {
    const float* edge_tokens     = (const float*)d_in[0];
    const float* question_tokens = (const float*)d_in[1];
    const int*   edge_batch      = (const int*)d_in[2];
    const int*   selected_mask   = (const int*)d_in[3];   // bool promoted to int32
    const float* W_edge          = (const float*)d_in[4];
    const float* W_query         = (const float*)d_in[5];
    const float* att_vec         = (const float*)d_in[6];
    const float* ln_g            = (const float*)d_in[7];
    const float* ln_b            = (const float*)d_in[8];
    const float* W1              = (const float*)d_in[9];
    const float* b1              = (const float*)d_in[10];
    const float* W2              = (const float*)d_in[11];
    const float* b2              = (const float*)d_in[12];

    float* out         = (float*)d_out;
    float* out_edge    = out;                 // [E]
    float* out_stop    = out + E_N;           // [G]
    float* out_pooled  = out + E_N + G_N;     // [G, H]

    kA_prep<<<dim3(8, 4), 256>>>(W_edge, W_query, att_vec);
    kB_qatt_seg<<<256, 256>>>(question_tokens, edge_batch);
    k3_edges<<<K3_GRID, K3_BLOCK>>>(edge_tokens, edge_batch, selected_mask);
    k4_fused<<<G_N, 256>>>(selected_mask, out_edge);
    k5_pool<<<dim3(8, 8), dim3(32, 32)>>>(W_edge, out_pooled);
    k6a_ln<<<G_N, 256>>>(out_pooled, question_tokens, ln_g, ln_b);
    k6b_mlp<<<dim3(8, 8), dim3(32, 32)>>>(W1, b1);
    k6c_stop<<<(G_N * 32 + 255) / 256, 256>>>(W2, b2, out_stop);
}

// round 7
// speedup vs baseline: 1.1664x; 1.0142x over previous
#include <cuda_runtime.h>
#include <math.h>

#define E_N 500000
#define G_N 256
#define H_N 256
#define H2_N 512
#define EPS_F 1.1920929e-07f
#define LOG_EPS -15.942385f
#define SEG_CAP 2560

// ---------------- scratch (device globals; no allocation allowed) ------------
__device__ float d_v_edge[H_N];        // att_vec @ W_edge
__device__ float d_v_query[H_N];       // att_vec @ W_query
__device__ float d_q_att[G_N];         // question · v_query  per graph
__device__ float d_att_raw[E_N];       // post-leaky/bonus attention logits
__device__ float d_sum_tok[G_N * H_N]; // segment sums of raw edge tokens
__device__ int   d_seg[G_N + 1];       // segment bounds (sorted edge_batch)
__device__ float d_xn[G_N * H2_N];     // LayerNorm output
__device__ float d_h1[G_N * H_N];      // GELU(MLP hidden)

// ---------------- kA: v_edge / v_query (parallel, j-split) + zero sum_tok ----
__global__ void kA_prep(const float* __restrict__ W_edge,
                        const float* __restrict__ W_query,
                        const float* __restrict__ att_vec) {
    int y = blockIdx.y;
    int tid = threadIdx.x;
    if (y >= 2) {
        int idx = (((y - 2) * 8) + blockIdx.x) * 256 + tid;
        for (int i = idx; i < G_N * H_N; i += 16 * 256) d_sum_tok[i] = 0.0f;
        return;
    }
    const float* W = (y == 0) ? W_edge : W_query;
    float* v       = (y == 0) ? d_v_edge : d_v_query;
    __shared__ float a[H_N];
    __shared__ float part[8][32];
    a[tid] = att_vec[tid];
    __syncthreads();
    int tt = tid & 31, jg = tid >> 5;
    int t0 = blockIdx.x * 32 + tt;
    float s = 0.f;
    #pragma unroll 8
    for (int j = jg * 32; j < jg * 32 + 32; ++j)
        s = fmaf(a[j], W[j * H_N + t0], s);
    part[jg][tt] = s;
    __syncthreads();
    if (jg == 0) {
        float r = part[0][tt] + part[1][tt] + part[2][tt] + part[3][tt]
                + part[4][tt] + part[5][tt] + part[6][tt] + part[7][tt];
        v[t0] = r;
    }
}

// ---------------- kB: q_att (blocks 0..31) + segment bounds (blocks 32..255) -
__global__ void kB_qatt_seg(const float* __restrict__ q,
                            const int* __restrict__ batch) {
    int b = blockIdx.x;
    if (b < 32) {
        int w = b * 8 + (threadIdx.x >> 5);  // graph index
        int lane = threadIdx.x & 31;
        const float4* q4 = (const float4*)(q + (size_t)w * H_N);
        const float4* v4 = (const float4*)d_v_query;
        float s = 0.f;
        #pragma unroll
        for (int k = 0; k < 2; ++k) {
            float4 t = q4[lane + 32 * k];
            float4 v = v4[lane + 32 * k];
            s += t.x * v.x + t.y * v.y + t.z * v.z + t.w * v.w;
        }
        #pragma unroll
        for (int o = 16; o; o >>= 1) s += __shfl_xor_sync(0xffffffffu, s, o);
        if (lane == 0) d_q_att[w] = s;
    } else {
        int idx = (b - 32) * 256 + threadIdx.x;
        int stride = (gridDim.x - 32) * 256;
        for (int e = idx; e < E_N; e += stride) {
            int bc = batch[e];
            int bp = (e == 0) ? -1 : batch[e - 1];
            for (int g = bp + 1; g <= bc; ++g) d_seg[g] = e;
            if (e == E_N - 1)
                for (int g = bc + 1; g <= G_N; ++g) d_seg[g] = E_N;
        }
    }
}

// ---------------- K3: dominant streaming pass over edge_tokens ---------------
#define K3_BLOCK 256
#define K3_GRID  592                    // 4 blocks/SM x 148 SMs
#define K3_WARPS (K3_GRID * (K3_BLOCK / 32))

__global__ __launch_bounds__(K3_BLOCK) void k3_edges(
        const float* __restrict__ tok,
        const int* __restrict__ batch,
        const int* __restrict__ sel) {
    int warp = (blockIdx.x * blockDim.x + threadIdx.x) >> 5;
    int lane = threadIdx.x & 31;
    const int chunk = (E_N + K3_WARPS - 1) / K3_WARPS;
    int e0 = warp * chunk;
    int e1 = min(e0 + chunk, E_N);
    if (e0 >= e1) return;

    float4 v0 = ((const float4*)d_v_edge)[lane];
    float4 v1 = ((const float4*)d_v_edge)[lane + 32];

    float4 a0 = make_float4(0.f, 0.f, 0.f, 0.f);
    float4 a1 = make_float4(0.f, 0.f, 0.f, 0.f);
    float keep = 0.f;                       // banked att value for this lane

    const float4* base = (const float4*)tok;
    float4 t0 = __ldcs(base + (size_t)e0 * 64 + lane);
    float4 t1 = __ldcs(base + (size_t)e0 * 64 + 32 + lane);
    int g  = batch[e0];
    int cg = g;

    for (int e = e0; e < e1; ++e) {
        float4 n0, n1; int ng = cg;
        if (e + 1 < e1) {
            n0 = __ldcs(base + (size_t)(e + 1) * 64 + lane);
            n1 = __ldcs(base + (size_t)(e + 1) * 64 + 32 + lane);
            ng = batch[e + 1];
        }
        if (g != cg) {  // segment boundary: flush partial sums
            float* dst = d_sum_tok + (size_t)cg * H_N;
            atomicAdd(&dst[4 * lane + 0], a0.x);
            atomicAdd(&dst[4 * lane + 1], a0.y);
            atomicAdd(&dst[4 * lane + 2], a0.z);
            atomicAdd(&dst[4 * lane + 3], a0.w);
            atomicAdd(&dst[128 + 4 * lane + 0], a1.x);
            atomicAdd(&dst[128 + 4 * lane + 1], a1.y);
            atomicAdd(&dst[128 + 4 * lane + 2], a1.z);
            atomicAdd(&dst[128 + 4 * lane + 3], a1.w);
            a0 = make_float4(0.f, 0.f, 0.f, 0.f);
            a1 = make_float4(0.f, 0.f, 0.f, 0.f);
            cg = g;
        }
        a0.x += t0.x; a0.y += t0.y; a0.z += t0.z; a0.w += t0.w;
        a1.x += t1.x; a1.y += t1.y; a1.z += t1.z; a1.w += t1.w;

        float d = t0.x * v0.x;
        d = fmaf(t0.y, v0.y, d); d = fmaf(t0.z, v0.z, d); d = fmaf(t0.w, v0.w, d);
        d = fmaf(t1.x, v1.x, d); d = fmaf(t1.y, v1.y, d);
        d = fmaf(t1.z, v1.z, d); d = fmaf(t1.w, v1.w, d);
        #pragma unroll
        for (int o = 16; o; o >>= 1) d += __shfl_xor_sync(0xffffffffu, d, o);
        // butterfly leaves the full sum in ALL lanes

        float att = d + d_q_att[g];
        att = att > 0.f ? att : 0.2f * att;             // LeakyReLU(0.2)
        if (sel[e] == 0) att += 0.5f;                   // frontier bonus
        if (lane == (e & 31)) keep = att;

        // coalesced 128B store every 32 edges (range-guarded at head/tail)
        if ((e & 31) == 31 || e == e1 - 1) {
            int bse = e & ~31;
            int idx = bse + lane;
            if (idx >= e0 && idx <= e)
                d_att_raw[idx] = keep;
        }

        t0 = n0; t1 = n1; g = ng;
    }
    float* dst = d_sum_tok + (size_t)cg * H_N;
    atomicAdd(&dst[4 * lane + 0], a0.x);
    atomicAdd(&dst[4 * lane + 1], a0.y);
    atomicAdd(&dst[4 * lane + 2], a0.z);
    atomicAdd(&dst[4 * lane + 3], a0.w);
    atomicAdd(&dst[128 + 4 * lane + 0], a1.x);
    atomicAdd(&dst[128 + 4 * lane + 1], a1.y);
    atomicAdd(&dst[128 + 4 * lane + 2], a1.z);
    atomicAdd(&dst[128 + 4 * lane + 3], a1.w);
}

// ---------------- K4: softmax stats + edge logits, smem-cached ---------------
__global__ __launch_bounds__(256) void k4_fused(const int* __restrict__ sel,
                                                float* __restrict__ out_edge) {
    int gi = blockIdx.x, t = threadIdx.x;
    int start = d_seg[gi], end = d_seg[gi + 1];
    int n = end - start;

    __shared__ float red[256];
    __shared__ float satt[SEG_CAP];
    __shared__ unsigned char smsk[SEG_CAP];

    if (n <= SEG_CAP) {
        // -------- cached path: one global read, three smem passes ----------
        #pragma unroll 4
        for (int i = t; i < n; i += 256) {
            satt[i] = d_att_raw[start + i];
            smsk[i] = (unsigned char)(sel[start + i] != 0);
        }
        __syncthreads();

        float mx = -INFINITY;
        for (int i = t; i < n; i += 256) mx = fmaxf(mx, satt[i]);
        red[t] = mx; __syncthreads();
        for (int s = 128; s; s >>= 1) { if (t < s) red[t] = fmaxf(red[t], red[t + s]); __syncthreads(); }
        mx = red[0];
        __syncthreads();

        float sm = 0.f;
        for (int i = t; i < n; i += 256)
            if (!smsk[i]) sm += expf(satt[i] - mx);
        red[t] = sm; __syncthreads();
        for (int s = 128; s; s >>= 1) { if (t < s) red[t] += red[t + s]; __syncthreads(); }
        float sub = mx + logf(fmaxf(red[0], EPS_F));

        for (int i = t; i < n; i += 256) {
            float v = LOG_EPS;
            if (!smsk[i]) v = fmaxf(satt[i] - sub, LOG_EPS);
            out_edge[start + i] = v;
        }
    } else {
        // -------- fallback: global passes (never expected for this dist) ---
        float mx = -INFINITY;
        for (int e = start + t; e < end; e += 256) mx = fmaxf(mx, d_att_raw[e]);
        red[t] = mx; __syncthreads();
        for (int s = 128; s; s >>= 1) { if (t < s) red[t] = fmaxf(red[t], red[t + s]); __syncthreads(); }
        mx = red[0];
        __syncthreads();

        float sm = 0.f;
        for (int e = start + t; e < end; e += 256)
            if (sel[e] == 0) sm += expf(d_att_raw[e] - mx);
        red[t] = sm; __syncthreads();
        for (int s = 128; s; s >>= 1) { if (t < s) red[t] += red[t + s]; __syncthreads(); }
        float sub = mx + logf(fmaxf(red[0], EPS_F));

        for (int e = start + t; e < end; e += 256) {
            float v = LOG_EPS;
            if (sel[e] == 0) v = fmaxf(d_att_raw[e] - sub, LOG_EPS);
            out_edge[e] = v;
        }
    }
}

// ---------------- K5: pooled = (sum_tok @ W_edge^T) / count  (tiled GEMM) ----
__global__ void k5_pool(const float* __restrict__ W_edge,
                        float* __restrict__ out_pool) {
    __shared__ float As[32][33], Ws[32][33];
    int tx = threadIdx.x, ty = threadIdx.y;
    float acc = 0.f;
    for (int kt = 0; kt < H_N; kt += 32) {
        As[ty][tx] = d_sum_tok[(blockIdx.y * 32 + ty) * H_N + kt + tx];
        Ws[ty][tx] = W_edge[(blockIdx.x * 32 + ty) * H_N + kt + tx];
        __syncthreads();
        #pragma unroll
        for (int kk = 0; kk < 32; ++kk) acc = fmaf(As[ty][kk], Ws[tx][kk], acc);
        __syncthreads();
    }
    int g = blockIdx.y * 32 + ty, j = blockIdx.x * 32 + tx;
    float invden = 1.0f / (float)max(d_seg[g + 1] - d_seg[g], 1);
    out_pool[g * H_N + j] = acc * invden;
}

// ---------------- K6a: LayerNorm over concat(pooled, question) ---------------
__global__ void k6a_ln(const float* __restrict__ pooled,
                       const float* __restrict__ q,
                       const float* __restrict__ ln_g,
                       const float* __restrict__ ln_b) {
    int g = blockIdx.x, t = threadIdx.x;
    float x0 = pooled[g * H_N + t];
    float x1 = q[g * H_N + t];
    __shared__ float rs[256], rss[256];
    rs[t]  = x0 + x1;
    rss[t] = x0 * x0 + x1 * x1;
    __syncthreads();
    for (int s = 128; s; s >>= 1) {
        if (t < s) { rs[t] += rs[t + s]; rss[t] += rss[t + s]; }
        __syncthreads();
    }
    float mu  = rs[0] * (1.0f / 512.0f);
    float var = rss[0] * (1.0f / 512.0f) - mu * mu;
    float inv = rsqrtf(var + 1e-5f);
    d_xn[g * H2_N + t]        = (x0 - mu) * inv * ln_g[t]        + ln_b[t];
    d_xn[g * H2_N + 256 + t]  = (x1 - mu) * inv * ln_g[256 + t]  + ln_b[256 + t];
}

// ---------------- K6b: h1 = GELU(xn @ W1^T + b1)  (tiled GEMM, K=512) --------
__global__ void k6b_mlp(const float* __restrict__ W1,
                        const float* __restrict__ b1) {
    __shared__ float As[32][33], Ws[32][33];
    int tx = threadIdx.x, ty = threadIdx.y;
    float acc = 0.f;
    for (int kt = 0; kt < H2_N; kt += 32) {
        As[ty][tx] = d_xn[(blockIdx.y * 32 + ty) * H2_N + kt + tx];
        Ws[ty][tx] = W1[(blockIdx.x * 32 + ty) * H2_N + kt + tx];
        __syncthreads();
        #pragma unroll
        for (int kk = 0; kk < 32; ++kk) acc = fmaf(As[ty][kk], Ws[tx][kk], acc);
        __syncthreads();
    }
    int g = blockIdx.y * 32 + ty, j = blockIdx.x * 32 + tx;
    float x = acc + b1[j];
    float gl = 0.5f * x * (1.0f + erff(x * 0.70710678118654752f)); // exact GELU
    d_h1[g * H_N + j] = gl;
}

// ---------------- K6c: stop_logits = h1 · W2 + b2  (warp per graph) ----------
__global__ void k6c_stop(const float* __restrict__ W2,
                         const float* __restrict__ b2,
                         float* __restrict__ out_stop) {
    int w = (blockIdx.x * blockDim.x + threadIdx.x) >> 5;
    int lane = threadIdx.x & 31;
    if (w >= G_N) return;
    const float4* h4 = (const float4*)(d_h1 + (size_t)w * H_N);
    const float4* w4 = (const float4*)W2;
    float s = 0.f;
    #pragma unroll
    for (int k = 0; k < 2; ++k) {
        float4 a = h4[lane + 32 * k];
        float4 b = w4[lane + 32 * k];
        s += a.x * b.x + a.y * b.y + a.z * b.z + a.w * b.w;
    }
    #pragma unroll
    for (int o = 16; o; o >>= 1) s += __shfl_xor_sync(0xffffffffu, s, o);
    if (lane == 0) out_stop[w] = s + b2[0];
}

// ---------------- launch -----------------------------------------------------
extern "C" void kernel_launch(void* const* d_in, const int* in_sizes, int n_in,
                              void* d_out, int out_size) {
    const float* edge_tokens     = (const float*)d_in[0];
    const float* question_tokens = (const float*)d_in[1];
    const int*   edge_batch      = (const int*)d_in[2];
    const int*   selected_mask   = (const int*)d_in[3];   // bool promoted to int32
    const float* W_edge          = (const float*)d_in[4];
    const float* W_query         = (const float*)d_in[5];
    const float* att_vec         = (const float*)d_in[6];
    const float* ln_g            = (const float*)d_in[7];
    const float* ln_b            = (const float*)d_in[8];
    const float* W1              = (const float*)d_in[9];
    const float* b1              = (const float*)d_in[10];
    const float* W2              = (const float*)d_in[11];
    const float* b2              = (const float*)d_in[12];

    float* out         = (float*)d_out;
    float* out_edge    = out;                 // [E]
    float* out_stop    = out + E_N;           // [G]
    float* out_pooled  = out + E_N + G_N;     // [G, H]

    kA_prep<<<dim3(8, 4), 256>>>(W_edge, W_query, att_vec);
    kB_qatt_seg<<<256, 256>>>(question_tokens, edge_batch);
    k3_edges<<<K3_GRID, K3_BLOCK>>>(edge_tokens, edge_batch, selected_mask);
    k4_fused<<<G_N, 256>>>(selected_mask, out_edge);
    k5_pool<<<dim3(8, 8), dim3(32, 32)>>>(W_edge, out_pooled);
    k6a_ln<<<G_N, 256>>>(out_pooled, question_tokens, ln_g, ln_b);
    k6b_mlp<<<dim3(8, 8), dim3(32, 32)>>>(W1, b1);
    k6c_stop<<<(G_N * 32 + 255) / 256, 256>>>(W2, b2, out_stop);
}